// round 1
// baseline (speedup 1.0000x reference)
#include <cuda_runtime.h>
#include <cuda_bf16.h>

// Shapes (fixed by the problem)
#define BB 256      // batch
#define MM 8        // metapaths
#define LL 64       // walk length
#define EE 128      // embedding
#define HH 8        // heads
#define HD 16       // head dim
#define JQKV 384    // 3*E

// Scratch (no cudaMalloc allowed)
__device__ float g_agg0[BB * MM * EE];          // [B,M,E]  1 MB
__device__ float g_agg1[BB * MM * EE];          // [B,M,E]  1 MB
__device__ float g_qkv[BB * MM * JQKV];         // [(b*8+m), 384]  3 MB

// packed f32x2 FMA (ptxas never auto-fuses this)
__device__ __forceinline__ unsigned long long ffma2(unsigned long long a,
                                                    unsigned long long b,
                                                    unsigned long long c) {
    unsigned long long d;
    asm("fma.rn.f32x2 %0, %1, %2, %3;" : "=l"(d) : "l"(a), "l"(b), "l"(c));
    return d;
}
__device__ __forceinline__ unsigned long long pack2(float lo, float hi) {
    unsigned long long d;
    asm("mov.b64 %0, {%1, %2};" : "=l"(d) : "f"(lo), "f"(hi));
    return d;
}
__device__ __forceinline__ void unpack2(unsigned long long v, float& lo, float& hi) {
    asm("mov.b64 {%0, %1}, %2;" : "=f"(lo), "=f"(hi) : "l"(v));
}

// ---------------------------------------------------------------------------
// K1: gather + elementwise fuse + mean over L.   grid = B*M blocks, 128 thr.
// agg0[b,m,e] = (1/L) * sum_l (nt[n1]+fb)*(nt[n2]+fb)*et[e]
// ---------------------------------------------------------------------------
__global__ __launch_bounds__(128) void k_gather(
    const int* __restrict__ walks,        // [B,M,L,3]
    const float* __restrict__ nt,         // [NUM_NODES, E]
    const float* __restrict__ fb,         // [E]
    const float* __restrict__ et)         // [8, E]
{
    __shared__ int   sw[LL * 3];
    __shared__ float se[8 * EE];
    const int t  = threadIdx.x;
    const int bm = blockIdx.x;

    for (int i = t; i < LL * 3; i += 128) sw[i] = walks[bm * (LL * 3) + i];
    for (int i = t; i < 8 * EE; i += 128) se[i] = et[i];
    const float fbv = fb[t];
    __syncthreads();

    float acc = 0.0f;
#pragma unroll 4
    for (int l = 0; l < LL; ++l) {
        const int n1 = sw[3 * l + 0];
        const int n2 = sw[3 * l + 1];
        const int ee = sw[3 * l + 2];
        const float a = nt[n1 * EE + t] + fbv;
        const float b = nt[n2 * EE + t] + fbv;
        acc += a * b * se[ee * EE + t];
    }
    g_agg0[bm * EE + t] = acc * (1.0f / (float)LL);
}

// ---------------------------------------------------------------------------
// K2: per-metapath linear.  grid = (B/8, M), 128 thr.
// agg1[b,m,o] = sum_e agg0[b,m,e] * W_mp[wm,e,o] + b_mp[wm,o]
// ---------------------------------------------------------------------------
__global__ __launch_bounds__(128) void k_mp(
    const int* __restrict__ mpidx,
    const float* __restrict__ W,          // [M,E,E]
    const float* __restrict__ bmp)        // [M,E]
{
    __shared__ float As[8 * EE];
    const int t  = threadIdx.x;
    const int b0 = blockIdx.x * 8;
    const int m  = blockIdx.y;
    const int wm = mpidx[m];

    for (int i = t; i < 8 * EE; i += 128) {
        const int r = i >> 7, e = i & 127;
        As[i] = g_agg0[((b0 + r) * MM + m) * EE + e];
    }
    __syncthreads();

    float acc[8];
#pragma unroll
    for (int r = 0; r < 8; ++r) acc[r] = 0.0f;

    const float* Wm = W + wm * EE * EE;
    for (int e = 0; e < EE; ++e) {
        const float w = Wm[e * EE + t];
#pragma unroll
        for (int r = 0; r < 8; ++r) acc[r] += As[r * EE + e] * w;
    }
    const float bias = bmp[wm * EE + t];
#pragma unroll
    for (int r = 0; r < 8; ++r)
        g_agg1[((b0 + r) * MM + m) * EE + t] = acc[r] + bias;
}

// ---------------------------------------------------------------------------
// K3: QKV projection GEMM. rows = 2048 (b*8+m), cols = 384.
// grid = (2048/32, 3), 128 thr.  A transposed in smem (float4/f32x2 reads),
// W tile staged conflict-free (stride 33).
// qkv[row, j] = sum_e agg1[row, e] * Wqkv[j, e] + bqkv[j]
// ---------------------------------------------------------------------------
__global__ __launch_bounds__(128) void k_qkv(
    const float* __restrict__ Wq,         // [384, 128]
    const float* __restrict__ bq)         // [384]
{
    __shared__ float A_T[EE * 36];        // [e][r], stride 36 (16B aligned)
    __shared__ float Ws[128 * 33];        // [j][e-chunk], stride 33 (no conflicts)
    const int t  = threadIdx.x;
    const int r0 = blockIdx.x * 32;
    const int j0 = blockIdx.y * 128;

    for (int i = t; i < 32 * EE; i += 128) {
        const int r = i >> 7, e = i & 127;
        A_T[e * 36 + r] = g_agg1[(r0 + r) * EE + e];
    }

    unsigned long long acc2[16];
#pragma unroll
    for (int r = 0; r < 16; ++r) acc2[r] = 0ULL;

    for (int e0 = 0; e0 < EE; e0 += 32) {
        __syncthreads();
        for (int i = t; i < 128 * 32; i += 128) {
            const int j = i >> 5, e = i & 31;
            Ws[j * 33 + e] = Wq[(j0 + j) * EE + e0 + e];
        }
        __syncthreads();
#pragma unroll 4
        for (int e = 0; e < 32; ++e) {
            const float w = Ws[t * 33 + e];
            const unsigned long long ww = pack2(w, w);
            const ulonglong2* ap =
                (const ulonglong2*)&A_T[(e0 + e) * 36];
#pragma unroll
            for (int q = 0; q < 8; ++q) {
                ulonglong2 a = ap[q];                  // 4 floats = 2 f32x2
                acc2[2 * q + 0] = ffma2(a.x, ww, acc2[2 * q + 0]);
                acc2[2 * q + 1] = ffma2(a.y, ww, acc2[2 * q + 1]);
            }
        }
    }
    const float bias = bq[j0 + t];
#pragma unroll
    for (int q = 0; q < 16; ++q) {
        float lo, hi;
        unpack2(acc2[q], lo, hi);
        g_qkv[(r0 + 2 * q + 0) * JQKV + j0 + t] = lo + bias;
        g_qkv[(r0 + 2 * q + 1) * JQKV + j0 + t] = hi + bias;
    }
}

// ---------------------------------------------------------------------------
// K4: fused attention over M=8 + output projection.  grid = B blocks, 128 thr.
// out[m, b, o] = sum_c ( sum_n softmax_n(q_m·k_n/4) * v[n] )[c] * Wo[o,c] + bo[o]
// ---------------------------------------------------------------------------
__global__ __launch_bounds__(128) void k_attn(
    const float* __restrict__ Wo,         // [128,128]
    const float* __restrict__ bo,         // [128]
    float* __restrict__ out)              // [M,B,E]
{
    __shared__ float s_qkv[MM * JQKV];    // [m][384]
    __shared__ float s_att[HH * MM * MM]; // [h][m][n]
    __shared__ float s_o[MM * EE];        // [m][e]
    const int t = threadIdx.x;
    const int b = blockIdx.x;

    for (int i = t; i < MM * JQKV; i += 128)
        s_qkv[i] = g_qkv[b * (MM * JQKV) + i];
    __syncthreads();

    // scores + softmax: one (h,m) pair per thread (t < 64)
    if (t < 64) {
        const int h = t >> 3;
        const int m = t & 7;
        float sc[MM];
#pragma unroll
        for (int n = 0; n < MM; ++n) {
            float s = 0.0f;
#pragma unroll
            for (int d = 0; d < HD; ++d)
                s += s_qkv[m * JQKV + h * HD + d] *
                     s_qkv[n * JQKV + EE + h * HD + d];
            sc[n] = s * 0.25f;            // 1/sqrt(16)
        }
        float mx = sc[0];
#pragma unroll
        for (int n = 1; n < MM; ++n) mx = fmaxf(mx, sc[n]);
        float sum = 0.0f;
#pragma unroll
        for (int n = 0; n < MM; ++n) { sc[n] = __expf(sc[n] - mx); sum += sc[n]; }
        const float inv = 1.0f / sum;
#pragma unroll
        for (int n = 0; n < MM; ++n)
            s_att[(h * MM + m) * MM + n] = sc[n] * inv;
    }
    __syncthreads();

    // o[m][e] = sum_n att[h(e)][m][n] * v[n][e]
    {
        const int h = t >> 4;             // e = t, h = e/16
#pragma unroll
        for (int m = 0; m < MM; ++m) {
            float v = 0.0f;
#pragma unroll
            for (int n = 0; n < MM; ++n)
                v += s_att[(h * MM + m) * MM + n] * s_qkv[n * JQKV + 2 * EE + t];
            s_o[m * EE + t] = v;
        }
    }
    __syncthreads();

    // output projection: thread t = output col o
    float acc[MM];
#pragma unroll
    for (int m = 0; m < MM; ++m) acc[m] = 0.0f;
    for (int c = 0; c < EE; ++c) {
        const float w = Wo[t * EE + c];
#pragma unroll
        for (int m = 0; m < MM; ++m) acc[m] += s_o[m * EE + c] * w;
    }
    const float bias = bo[t];
#pragma unroll
    for (int m = 0; m < MM; ++m)
        out[(m * BB + b) * EE + t] = acc[m] + bias;
}

// ---------------------------------------------------------------------------
extern "C" void kernel_launch(void* const* d_in, const int* in_sizes, int n_in,
                              void* d_out, int out_size) {
    // metadata order:
    // 0 node_idx(int,unused) 1 mp_type_idx(int) 2 node_mp_walks(int)
    // 3 node_table 4 fc1_b 5 edge_table 6 W_mp 7 b_mp 8 Wqkv 9 bqkv 10 Wo 11 bo
    const int*   mp_type = (const int*)d_in[1];
    const int*   walks   = (const int*)d_in[2];
    const float* nt      = (const float*)d_in[3];
    const float* fb      = (const float*)d_in[4];
    const float* et      = (const float*)d_in[5];
    const float* W_mp    = (const float*)d_in[6];
    const float* b_mp    = (const float*)d_in[7];
    const float* Wqkv    = (const float*)d_in[8];
    const float* bqkv    = (const float*)d_in[9];
    const float* Wo      = (const float*)d_in[10];
    const float* bo      = (const float*)d_in[11];
    float* out = (float*)d_out;

    k_gather<<<BB * MM, 128>>>(walks, nt, fb, et);
    k_mp<<<dim3(BB / 8, MM), 128>>>(mp_type, W_mp, b_mp);
    k_qkv<<<dim3((BB * MM) / 32, 3), 128>>>(Wqkv, bqkv);
    k_attn<<<BB, 128>>>(Wo, bo, out);
}